// round 2
// baseline (speedup 1.0000x reference)
#include <cuda_runtime.h>
#include <cstddef>

#define BB   16
#define NPTS 10000
#define HID  128
#define OUTD 5
#define PTS  256          // points per trunk block
#define NTILE 40          // ceil(10000/256)
#define ACTP 132          // padded act row (floats), multiple of 4, +4 skew

// scratch written by branch kernel, read by trunk kernel
__device__ float g_gate[BB * 4 * HID];
__device__ float g_bc[BB * OUTD * HID];

__device__ __forceinline__ float tanh_ap(float x) {
    float r; asm("tanh.approx.f32 %0, %1;" : "=f"(r) : "f"(x)); return r;
}
__device__ __forceinline__ float sin_ap(float x) {
    float r; asm("sin.approx.f32 %0, %1;" : "=f"(r) : "f"(x)); return r;
}

// ---------------------------------------------------------------------------
// Branch MLP: 16 blocks (one per batch row) x 128 threads (one per feature).
// Writes running-sum gates and the reshaped branch output bc[b][o][h].
// ---------------------------------------------------------------------------
__global__ void branch_kernel(const float* __restrict__ params,
                              const float* __restrict__ Wb0, const float* __restrict__ bb0,
                              const float* __restrict__ Wb,  const float* __restrict__ bbv,
                              const float* __restrict__ Wbf, const float* __restrict__ bbf,
                              const float* __restrict__ ab,  const float* __restrict__ wb)
{
    __shared__ float h_s[HID];
    const int b = blockIdx.x;
    const int j = threadIdx.x;

    float z = bb0[j];
#pragma unroll
    for (int c = 0; c < 6; ++c) z = fmaf(params[b * 6 + c], Wb0[c * HID + j], z);
    float h = tanh_ap(z) + ab[j] * sin_ap(wb[j] * z);
    float g = h;
    g_gate[(b * 4 + 0) * HID + j] = g;
    h_s[j] = h;
    __syncthreads();

    for (int i = 0; i < 3; ++i) {
        float zz = bbv[i * HID + j];
        const float* W = Wb + (size_t)i * HID * HID;
#pragma unroll 4
        for (int k = 0; k < HID; ++k) zz = fmaf(h_s[k], W[k * HID + j], zz);
        float hh = tanh_ap(zz) + ab[(i + 1) * HID + j] * sin_ap(wb[(i + 1) * HID + j] * zz);
        g += hh;
        g_gate[(b * 4 + i + 1) * HID + j] = g;
        __syncthreads();
        h_s[j] = hh;
        __syncthreads();
    }

#pragma unroll
    for (int o = 0; o < OUTD; ++o) {
        float zz = bbf[o * HID + j];
#pragma unroll 4
        for (int k = 0; k < HID; ++k)
            zz = fmaf(h_s[k], Wbf[(size_t)k * (HID * OUTD) + o * HID + j], zz);
        g_bc[(b * OUTD + o) * HID + j] = zz;
    }
}

// ---------------------------------------------------------------------------
// Fused trunk: per block 256 points of one batch row. Activations live in
// SMEM across all 5 layers; layer weights staged into SMEM per layer.
// Thread (j = tid&127, pg = tid>>7) computes feature j for 16 points/subtile.
// Ends with the 128->5 contraction against bc and writes the final output.
// ---------------------------------------------------------------------------
__global__ void __launch_bounds__(256, 1)
trunk_kernel(const float* __restrict__ coords, const float* __restrict__ sdf,
             const float* __restrict__ Wt0, const float* __restrict__ bt0,
             const float* __restrict__ Wt,  const float* __restrict__ btv,
             const float* __restrict__ Wtf, const float* __restrict__ btf,
             const float* __restrict__ at,  const float* __restrict__ wt,
             float* __restrict__ out)
{
    extern __shared__ float sm[];
    float* sW    = sm;                    // 128*128       = 16384
    float* sAct  = sW   + HID * HID;      // 256*132       = 33792
    float* sXin  = sAct + PTS * ACTP;     // 256*4         = 1024
    float* sGate = sXin + PTS * 4;        // 4*128         = 512
    float* sBC   = sGate + 4 * HID;       // 5*128         = 640
    // total 52352 floats = 209408 bytes

    const int b   = blockIdx.y;
    const int p0  = blockIdx.x * PTS;
    const int tid = threadIdx.x;
    const int j   = tid & (HID - 1);
    const int pg  = tid >> 7;

    // stage inputs: coords+sdf for this block's 256 points
    {
        int p = p0 + tid;
        float4 v = make_float4(0.f, 0.f, 0.f, 0.f);
        if (p < NPTS) {
            const float* c = coords + ((size_t)b * NPTS + p) * 3;
            v.x = c[0]; v.y = c[1]; v.z = c[2];
            v.w = sdf[(size_t)b * NPTS + p];
        }
        ((float4*)sXin)[tid] = v;
    }
    for (int i = tid; i < 4 * HID;    i += 256) sGate[i] = g_gate[b * 4 * HID + i];
    for (int i = tid; i < OUTD * HID; i += 256) sBC[i]   = g_bc[b * OUTD * HID + i];

    // layer-0 weights/scalars in registers
    float w00 = Wt0[0 * HID + j], w01 = Wt0[1 * HID + j];
    float w02 = Wt0[2 * HID + j], w03 = Wt0[3 * HID + j];
    float bias = bt0[j], aj = at[j], wj = wt[j];
    __syncthreads();
    float gj = sGate[j];

    // ---- layer 0: (coords,sdf) -> 128, rowdy * gate0 ----
#pragma unroll
    for (int st = 0; st < 8; ++st) {
        int pbase = st * 32 + pg * 16;
#pragma unroll
        for (int p = 0; p < 16; ++p) {
            float4 xv = ((float4*)sXin)[pbase + p];
            float z = fmaf(xv.x, w00, fmaf(xv.y, w01, fmaf(xv.z, w02, fmaf(xv.w, w03, bias))));
            float r = tanh_ap(z) + aj * sin_ap(wj * z);
            sAct[(pbase + p) * ACTP + j] = r * gj;
        }
    }

    // ---- layers 1..3 (rowdy*gate) and final linear layer (Wtf) ----
    for (int layer = 0; layer < 4; ++layer) {
        const float* Wsrc = (layer < 3) ? (Wt + (size_t)layer * HID * HID) : Wtf;
        const bool finalL = (layer == 3);

        __syncthreads();                       // prior act writes + prior sW reads done
        for (int i = tid; i < (HID * HID) / 4; i += 256)
            ((float4*)sW)[i] = ((const float4*)Wsrc)[i];
        if (!finalL) {
            bias = btv[layer * HID + j];
            aj   = at[(layer + 1) * HID + j];
            wj   = wt[(layer + 1) * HID + j];
            gj   = sGate[(layer + 1) * HID + j];
        } else {
            bias = btf[j];
        }
        __syncthreads();                       // sW ready

        for (int st = 0; st < 8; ++st) {
            const int pbase = st * 32 + pg * 16;
            float acc[16];
#pragma unroll
            for (int p = 0; p < 16; ++p) acc[p] = 0.f;

#pragma unroll 2
            for (int k = 0; k < HID; k += 4) {
                float v0 = sW[(k + 0) * HID + j];
                float v1 = sW[(k + 1) * HID + j];
                float v2 = sW[(k + 2) * HID + j];
                float v3 = sW[(k + 3) * HID + j];
#pragma unroll
                for (int p = 0; p < 16; ++p) {
                    float4 a = *(const float4*)&sAct[(pbase + p) * ACTP + k];
                    acc[p] = fmaf(a.x, v0, acc[p]);
                    acc[p] = fmaf(a.y, v1, acc[p]);
                    acc[p] = fmaf(a.z, v2, acc[p]);
                    acc[p] = fmaf(a.w, v3, acc[p]);
                }
            }
            __syncthreads();                   // all reads of these rows done before writes
            if (!finalL) {
#pragma unroll
                for (int p = 0; p < 16; ++p) {
                    float z = acc[p] + bias;
                    float r = tanh_ap(z) + aj * sin_ap(wj * z);
                    sAct[(pbase + p) * ACTP + j] = r * gj;
                }
            } else {
#pragma unroll
                for (int p = 0; p < 16; ++p)
                    sAct[(pbase + p) * ACTP + j] = acc[p] + bias;
            }
        }
    }
    __syncthreads();

    // ---- final contraction: out[p][o] = sum_h trunk[p][h] * bc[o][h] ----
    {
        const int p = tid;
        float o0 = 0.f, o1 = 0.f, o2 = 0.f, o3 = 0.f, o4 = 0.f;
#pragma unroll 4
        for (int h = 0; h < HID; h += 4) {
            float4 a  = *(const float4*)&sAct[p * ACTP + h];
            float4 c0 = *(const float4*)&sBC[0 * HID + h];
            float4 c1 = *(const float4*)&sBC[1 * HID + h];
            float4 c2 = *(const float4*)&sBC[2 * HID + h];
            float4 c3 = *(const float4*)&sBC[3 * HID + h];
            float4 c4 = *(const float4*)&sBC[4 * HID + h];
            o0 += a.x * c0.x + a.y * c0.y + a.z * c0.z + a.w * c0.w;
            o1 += a.x * c1.x + a.y * c1.y + a.z * c1.z + a.w * c1.w;
            o2 += a.x * c2.x + a.y * c2.y + a.z * c2.z + a.w * c2.w;
            o3 += a.x * c3.x + a.y * c3.y + a.z * c3.z + a.w * c3.w;
            o4 += a.x * c4.x + a.y * c4.y + a.z * c4.z + a.w * c4.w;
        }
        const int pglob = p0 + p;
        if (pglob < NPTS) {
            float* dst = out + ((size_t)b * NPTS + pglob) * OUTD;
            dst[0] = o0; dst[1] = o1; dst[2] = o2; dst[3] = o3; dst[4] = o4;
        }
    }
}

// ---------------------------------------------------------------------------
extern "C" void kernel_launch(void* const* d_in, const int* in_sizes, int n_in,
                              void* d_out, int out_size)
{
    const float* coords = (const float*)d_in[0];
    const float* sdf    = (const float*)d_in[1];
    const float* params = (const float*)d_in[2];
    const float* Wb0    = (const float*)d_in[3];
    const float* bb0    = (const float*)d_in[4];
    const float* Wb     = (const float*)d_in[5];
    const float* bbv    = (const float*)d_in[6];
    const float* Wbf    = (const float*)d_in[7];
    const float* bbf    = (const float*)d_in[8];
    const float* ab     = (const float*)d_in[9];
    const float* wb     = (const float*)d_in[10];
    const float* Wt0    = (const float*)d_in[11];
    const float* bt0    = (const float*)d_in[12];
    const float* Wt     = (const float*)d_in[13];
    const float* bt     = (const float*)d_in[14];
    const float* Wtf    = (const float*)d_in[15];
    const float* btf    = (const float*)d_in[16];
    const float* at     = (const float*)d_in[17];
    const float* wt     = (const float*)d_in[18];
    float* out = (float*)d_out;

    const size_t smem_bytes = (size_t)(HID * HID + PTS * ACTP + PTS * 4 + 4 * HID + OUTD * HID) * sizeof(float);
    cudaFuncSetAttribute(trunk_kernel, cudaFuncAttributeMaxDynamicSharedMemorySize, (int)smem_bytes);

    branch_kernel<<<BB, HID>>>(params, Wb0, bb0, Wb, bbv, Wbf, bbf, ab, wb);

    dim3 grid(NTILE, BB);
    trunk_kernel<<<grid, 256, smem_bytes>>>(coords, sdf, Wt0, bt0, Wt, bt,
                                            Wtf, btf, at, wt, out);
}

// round 3
// speedup vs baseline: 1.4023x; 1.4023x over previous
#include <cuda_runtime.h>
#include <cstddef>

#define BB   16
#define NPTS 10000
#define HID  128
#define OUTD 5
#define PTS  256          // points per trunk block
#define NTILE 40          // ceil(10000/256)
#define ACTP 132          // padded act row (floats)
#define THR  512

// scratch written by branch kernel, read by trunk kernel
__device__ float g_gate[BB * 4 * HID];
__device__ float g_bc[BB * OUTD * HID];

__device__ __forceinline__ float tanh_ap(float x) {
    float r; asm("tanh.approx.f32 %0, %1;" : "=f"(r) : "f"(x)); return r;
}
__device__ __forceinline__ float sin_ap(float x) {
    float r; asm("sin.approx.f32 %0, %1;" : "=f"(r) : "f"(x)); return r;
}
__device__ __forceinline__ void bar_grp(int id) {
    asm volatile("bar.sync %0, 64;" :: "r"(id) : "memory");
}

// ---------------------------------------------------------------------------
// Branch MLP: 16 blocks x 128 threads. Tiny; unchanged from R2.
// ---------------------------------------------------------------------------
__global__ void branch_kernel(const float* __restrict__ params,
                              const float* __restrict__ Wb0, const float* __restrict__ bb0,
                              const float* __restrict__ Wb,  const float* __restrict__ bbv,
                              const float* __restrict__ Wbf, const float* __restrict__ bbf,
                              const float* __restrict__ ab,  const float* __restrict__ wb)
{
    __shared__ float h_s[HID];
    const int b = blockIdx.x;
    const int j = threadIdx.x;

    float z = bb0[j];
#pragma unroll
    for (int c = 0; c < 6; ++c) z = fmaf(params[b * 6 + c], Wb0[c * HID + j], z);
    float h = tanh_ap(z) + ab[j] * sin_ap(wb[j] * z);
    float g = h;
    g_gate[(b * 4 + 0) * HID + j] = g;
    h_s[j] = h;
    __syncthreads();

    for (int i = 0; i < 3; ++i) {
        float zz = bbv[i * HID + j];
        const float* W = Wb + (size_t)i * HID * HID;
#pragma unroll 4
        for (int k = 0; k < HID; ++k) zz = fmaf(h_s[k], W[k * HID + j], zz);
        float hh = tanh_ap(zz) + ab[(i + 1) * HID + j] * sin_ap(wb[(i + 1) * HID + j] * zz);
        g += hh;
        g_gate[(b * 4 + i + 1) * HID + j] = g;
        __syncthreads();
        h_s[j] = hh;
        __syncthreads();
    }

#pragma unroll
    for (int o = 0; o < OUTD; ++o) {
        float zz = bbf[o * HID + j];
#pragma unroll 4
        for (int k = 0; k < HID; ++k)
            zz = fmaf(h_s[k], Wbf[(size_t)k * (HID * OUTD) + o * HID + j], zz);
        g_bc[(b * OUTD + o) * HID + j] = zz;
    }
}

// ---------------------------------------------------------------------------
// Fused trunk, 512 threads. Thread (jj = tid&63, pg = tid>>6) computes
// features {2jj, 2jj+1} for 8 points per subtile (4 subtiles of 64 points).
// Point rows are partitioned by pg-group (64 threads), so the in-layer
// read->overwrite hazard is intra-group: named bar.sync(pg+1, 64) only.
// ---------------------------------------------------------------------------
__global__ void __launch_bounds__(THR, 1)
trunk_kernel(const float* __restrict__ coords, const float* __restrict__ sdf,
             const float* __restrict__ Wt0, const float* __restrict__ bt0,
             const float* __restrict__ Wt,  const float* __restrict__ btv,
             const float* __restrict__ Wtf, const float* __restrict__ btf,
             const float* __restrict__ at,  const float* __restrict__ wt,
             float* __restrict__ out)
{
    extern __shared__ float sm[];
    float* sW    = sm;                    // 128*128  = 16384
    float* sAct  = sW   + HID * HID;      // 256*132  = 33792
    float* sXin  = sAct + PTS * ACTP;     // 256*4    = 1024
    float* sGate = sXin + PTS * 4;        // 4*128    = 512
    float* sBC   = sGate + 4 * HID;       // 5*128    = 640
    // total 52352 floats = 209408 bytes

    const int b   = blockIdx.y;
    const int p0  = blockIdx.x * PTS;
    const int tid = threadIdx.x;
    const int jj  = tid & 63;
    const int f0  = jj * 2;
    const int f1  = f0 + 1;
    const int pg  = tid >> 6;             // 0..7

    // stage inputs
    if (tid < PTS) {
        int p = p0 + tid;
        float4 v = make_float4(0.f, 0.f, 0.f, 0.f);
        if (p < NPTS) {
            const float* c = coords + ((size_t)b * NPTS + p) * 3;
            v.x = c[0]; v.y = c[1]; v.z = c[2];
            v.w = sdf[(size_t)b * NPTS + p];
        }
        ((float4*)sXin)[tid] = v;
    }
    for (int i = tid; i < 4 * HID;    i += THR) sGate[i] = g_gate[b * 4 * HID + i];
    for (int i = tid; i < OUTD * HID; i += THR) sBC[i]   = g_bc[b * OUTD * HID + i];

    // layer-0 weights/scalars for this thread's 2 features
    float w0a[4], w0b[4];
#pragma unroll
    for (int c = 0; c < 4; ++c) { w0a[c] = Wt0[c * HID + f0]; w0b[c] = Wt0[c * HID + f1]; }
    float bias0 = bt0[f0], bias1 = bt0[f1];
    float aj0 = at[f0], aj1 = at[f1];
    float wj0 = wt[f0], wj1 = wt[f1];
    __syncthreads();
    float gj0 = sGate[f0], gj1 = sGate[f1];

    // ---- layer 0: (coords,sdf) -> 128, rowdy * gate0 ----
#pragma unroll
    for (int st = 0; st < 4; ++st) {
        const int pbase = st * 64 + pg * 8;
#pragma unroll
        for (int p = 0; p < 8; ++p) {
            float4 xv = ((float4*)sXin)[pbase + p];
            float za = fmaf(xv.x, w0a[0], fmaf(xv.y, w0a[1], fmaf(xv.z, w0a[2], fmaf(xv.w, w0a[3], bias0))));
            float zb = fmaf(xv.x, w0b[0], fmaf(xv.y, w0b[1], fmaf(xv.z, w0b[2], fmaf(xv.w, w0b[3], bias1))));
            float ra = tanh_ap(za) + aj0 * sin_ap(wj0 * za);
            float rb = tanh_ap(zb) + aj1 * sin_ap(wj1 * zb);
            float* row = sAct + (pbase + p) * ACTP;
            row[f0] = ra * gj0;
            row[f1] = rb * gj1;
        }
    }

    // ---- layers 1..3 (rowdy*gate) and final linear (Wtf) ----
    for (int layer = 0; layer < 4; ++layer) {
        const float* Wsrc = (layer < 3) ? (Wt + (size_t)layer * HID * HID) : Wtf;
        const bool finalL = (layer == 3);

        __syncthreads();                       // all act writes + prior sW reads done
        for (int i = tid; i < (HID * HID) / 4; i += THR)
            ((float4*)sW)[i] = ((const float4*)Wsrc)[i];
        if (!finalL) {
            bias0 = btv[layer * HID + f0];  bias1 = btv[layer * HID + f1];
            aj0 = at[(layer + 1) * HID + f0]; aj1 = at[(layer + 1) * HID + f1];
            wj0 = wt[(layer + 1) * HID + f0]; wj1 = wt[(layer + 1) * HID + f1];
            gj0 = sGate[(layer + 1) * HID + f0]; gj1 = sGate[(layer + 1) * HID + f1];
        } else {
            bias0 = btf[f0]; bias1 = btf[f1];
        }
        __syncthreads();                       // sW ready

#pragma unroll
        for (int st = 0; st < 4; ++st) {
            const int pbase = st * 64 + pg * 8;
            float* actrow = sAct + pbase * ACTP;

            float acc0[8], acc1[8];
#pragma unroll
            for (int p = 0; p < 8; ++p) { acc0[p] = 0.f; acc1[p] = 0.f; }

#pragma unroll 2
            for (int k = 0; k < HID; k += 4) {
                const float* wp = sW + k * HID;
                float wa0 = wp[f0],           wb0_ = wp[f1];
                float wa1 = wp[HID + f0],     wb1_ = wp[HID + f1];
                float wa2 = wp[2 * HID + f0], wb2_ = wp[2 * HID + f1];
                float wa3 = wp[3 * HID + f0], wb3_ = wp[3 * HID + f1];
#pragma unroll
                for (int p = 0; p < 8; ++p) {
                    float4 a = *(const float4*)(actrow + p * ACTP + k);
                    acc0[p] = fmaf(a.x, wa0, acc0[p]);
                    acc1[p] = fmaf(a.x, wb0_, acc1[p]);
                    acc0[p] = fmaf(a.y, wa1, acc0[p]);
                    acc1[p] = fmaf(a.y, wb1_, acc1[p]);
                    acc0[p] = fmaf(a.z, wa2, acc0[p]);
                    acc1[p] = fmaf(a.z, wb2_, acc1[p]);
                    acc0[p] = fmaf(a.w, wa3, acc0[p]);
                    acc1[p] = fmaf(a.w, wb3_, acc1[p]);
                }
            }

            bar_grp(pg + 1);                   // group's reads of these rows done
            if (!finalL) {
#pragma unroll
                for (int p = 0; p < 8; ++p) {
                    float za = acc0[p] + bias0;
                    float zb = acc1[p] + bias1;
                    float ra = tanh_ap(za) + aj0 * sin_ap(wj0 * za);
                    float rb = tanh_ap(zb) + aj1 * sin_ap(wj1 * zb);
                    float* row = actrow + p * ACTP;
                    row[f0] = ra * gj0;
                    row[f1] = rb * gj1;
                }
            } else {
#pragma unroll
                for (int p = 0; p < 8; ++p) {
                    float* row = actrow + p * ACTP;
                    row[f0] = acc0[p] + bias0;
                    row[f1] = acc1[p] + bias1;
                }
            }
            bar_grp(pg + 1);                   // writes visible before next layer's reads
        }
    }
    __syncthreads();

    // ---- final contraction: out[p][o] = sum_h trunk[p][h] * bc[o][h] ----
    if (tid < PTS) {
        const int p = tid;
        float o0 = 0.f, o1 = 0.f, o2 = 0.f, o3 = 0.f, o4 = 0.f;
#pragma unroll 4
        for (int h = 0; h < HID; h += 4) {
            float4 a  = *(const float4*)&sAct[p * ACTP + h];
            float4 c0 = *(const float4*)&sBC[0 * HID + h];
            float4 c1 = *(const float4*)&sBC[1 * HID + h];
            float4 c2 = *(const float4*)&sBC[2 * HID + h];
            float4 c3 = *(const float4*)&sBC[3 * HID + h];
            float4 c4 = *(const float4*)&sBC[4 * HID + h];
            o0 += a.x * c0.x + a.y * c0.y + a.z * c0.z + a.w * c0.w;
            o1 += a.x * c1.x + a.y * c1.y + a.z * c1.z + a.w * c1.w;
            o2 += a.x * c2.x + a.y * c2.y + a.z * c2.z + a.w * c2.w;
            o3 += a.x * c3.x + a.y * c3.y + a.z * c3.z + a.w * c3.w;
            o4 += a.x * c4.x + a.y * c4.y + a.z * c4.z + a.w * c4.w;
        }
        const int pglob = p0 + p;
        if (pglob < NPTS) {
            float* dst = out + ((size_t)b * NPTS + pglob) * OUTD;
            dst[0] = o0; dst[1] = o1; dst[2] = o2; dst[3] = o3; dst[4] = o4;
        }
    }
}

// ---------------------------------------------------------------------------
extern "C" void kernel_launch(void* const* d_in, const int* in_sizes, int n_in,
                              void* d_out, int out_size)
{
    const float* coords = (const float*)d_in[0];
    const float* sdf    = (const float*)d_in[1];
    const float* params = (const float*)d_in[2];
    const float* Wb0    = (const float*)d_in[3];
    const float* bb0    = (const float*)d_in[4];
    const float* Wb     = (const float*)d_in[5];
    const float* bbv    = (const float*)d_in[6];
    const float* Wbf    = (const float*)d_in[7];
    const float* bbf    = (const float*)d_in[8];
    const float* ab     = (const float*)d_in[9];
    const float* wb     = (const float*)d_in[10];
    const float* Wt0    = (const float*)d_in[11];
    const float* bt0    = (const float*)d_in[12];
    const float* Wt     = (const float*)d_in[13];
    const float* bt     = (const float*)d_in[14];
    const float* Wtf    = (const float*)d_in[15];
    const float* btf    = (const float*)d_in[16];
    const float* at     = (const float*)d_in[17];
    const float* wt     = (const float*)d_in[18];
    float* out = (float*)d_out;

    const size_t smem_bytes = (size_t)(HID * HID + PTS * ACTP + PTS * 4 + 4 * HID + OUTD * HID) * sizeof(float);
    cudaFuncSetAttribute(trunk_kernel, cudaFuncAttributeMaxDynamicSharedMemorySize, (int)smem_bytes);

    branch_kernel<<<BB, HID>>>(params, Wb0, bb0, Wb, bbv, Wbf, bbf, ab, wb);

    dim3 grid(NTILE, BB);
    trunk_kernel<<<grid, THR, smem_bytes>>>(coords, sdf, Wt0, bt0, Wt, bt,
                                            Wtf, btf, at, wt, out);
}

// round 5
// speedup vs baseline: 2.0652x; 1.4728x over previous
#include <cuda_runtime.h>
#include <cstddef>

#define BB   16
#define NPTS 10000
#define HID  128
#define OUTD 5
#define PTS  128
#define NT   79            // ceil(10000/128)
#define THR  512
#define ACTP 132           // plain-layout row stride for final stage

typedef unsigned long long u64;

__device__ float g_gate[BB * 4 * HID];
__device__ float g_bc[BB * OUTD * HID];

__device__ __forceinline__ float tanh_ap(float x) {
    float r; asm("tanh.approx.f32 %0, %1;" : "=f"(r) : "f"(x)); return r;
}
__device__ __forceinline__ float sin_ap(float x) {
    float r; asm("sin.approx.f32 %0, %1;" : "=f"(r) : "f"(x)); return r;
}
__device__ __forceinline__ u64 pk2(float x, float y) {
    u64 r; asm("mov.b64 %0, {%1, %2};" : "=l"(r) : "f"(x), "f"(y)); return r;
}
__device__ __forceinline__ float2 up2(u64 v) {
    float2 r; asm("mov.b64 {%0, %1}, %2;" : "=f"(r.x), "=f"(r.y) : "l"(v)); return r;
}
__device__ __forceinline__ void fma2(u64& d, u64 a, u64 b) {
    asm("fma.rn.f32x2 %0, %1, %2, %0;" : "+l"(d) : "l"(a), "l"(b));
}

// ---------------------------------------------------------------------------
// Branch MLP: 16 blocks x 256 threads (k split in half to shorten the serial
// FMA chain). Writes running-sum gates and bc[b][o][h].
// ---------------------------------------------------------------------------
__global__ void branch_kernel(const float* __restrict__ params,
                              const float* __restrict__ Wb0, const float* __restrict__ bb0,
                              const float* __restrict__ Wb,  const float* __restrict__ bbv,
                              const float* __restrict__ Wbf, const float* __restrict__ bbf,
                              const float* __restrict__ ab,  const float* __restrict__ wb)
{
    __shared__ float h_s[HID];
    __shared__ float part[HID];
    const int b = blockIdx.x, tid = threadIdx.x;
    const int j = tid & 127, hh = tid >> 7;

    float g = 0.f;
    if (hh == 0) {
        float z = bb0[j];
#pragma unroll
        for (int c = 0; c < 6; ++c) z = fmaf(params[b * 6 + c], Wb0[c * HID + j], z);
        float v = tanh_ap(z) + ab[j] * sin_ap(wb[j] * z);
        g = v; g_gate[(b * 4) * HID + j] = g; h_s[j] = v;
    }
    __syncthreads();

    for (int i = 0; i < 3; ++i) {
        const float* W = Wb + (size_t)i * HID * HID;
        float zz = (hh == 0) ? bbv[i * HID + j] : 0.f;
        const int k0 = hh * 64;
#pragma unroll 4
        for (int k = 0; k < 64; ++k) zz = fmaf(h_s[k0 + k], W[(size_t)(k0 + k) * HID + j], zz);
        if (hh) part[j] = zz;
        __syncthreads();
        float v = 0.f;
        if (hh == 0) {
            float z = zz + part[j];
            v = tanh_ap(z) + ab[(i + 1) * HID + j] * sin_ap(wb[(i + 1) * HID + j] * z);
            g += v; g_gate[(b * 4 + i + 1) * HID + j] = g;
        }
        __syncthreads();
        if (hh == 0) h_s[j] = v;
        __syncthreads();
    }

#pragma unroll
    for (int o = 0; o < OUTD; ++o) {
        float zz = (hh == 0) ? bbf[o * HID + j] : 0.f;
        const int k0 = hh * 64;
#pragma unroll 4
        for (int k = 0; k < 64; ++k)
            zz = fmaf(h_s[k0 + k], Wbf[(size_t)(k0 + k) * (HID * OUTD) + o * HID + j], zz);
        if (hh) part[j] = zz;
        __syncthreads();
        if (hh == 0) g_bc[(b * OUTD + o) * HID + j] = zz + part[j];
        __syncthreads();
    }
}

// ---------------------------------------------------------------------------
// Fused trunk, 512 threads, PTS=128. Warp w owns points [8w, 8w+8) = 4 pairs.
// Lane owns 4 features f0=4*lane. Activations in pair-interleaved SMEM layout
// ([pair][k][2]) so each LDS.128 yields two f32x2 operands directly. GEMM uses
// packed fma.rn.f32x2 (2 FMAs/instr). In-layer act hazards are warp-private.
// ---------------------------------------------------------------------------
__global__ void __launch_bounds__(THR, 1)
trunk_kernel(const float* __restrict__ coords, const float* __restrict__ sdf,
             const float* __restrict__ Wt0, const float* __restrict__ bt0,
             const float* __restrict__ Wt,  const float* __restrict__ btv,
             const float* __restrict__ Wtf, const float* __restrict__ btf,
             const float* __restrict__ at,  const float* __restrict__ wt,
             float* __restrict__ out)
{
    extern __shared__ float sm[];
    float* sW = sm;                   // 128*128 = 16384
    float* sA = sW + HID * HID;       // max(64*256, 128*132) = 16896
    float* sX = sA + 16896;           // 128*4 = 512
    float* sG = sX + PTS * 4;         // 512
    float* sC = sG + 4 * HID;         // 640
    // total 34944 floats = 139776 bytes

    const int b   = blockIdx.y;
    const int p0  = blockIdx.x * PTS;
    const int tid = threadIdx.x;
    const int w   = tid >> 5;         // warp 0..15
    const int lane = tid & 31;
    const int f0  = lane * 4;

    // stage inputs
    if (tid < PTS) {
        int p = p0 + tid;
        float4 v = make_float4(0.f, 0.f, 0.f, 0.f);
        if (p < NPTS) {
            const float* c = coords + ((size_t)b * NPTS + p) * 3;
            v.x = c[0]; v.y = c[1]; v.z = c[2];
            v.w = sdf[(size_t)b * NPTS + p];
        }
        ((float4*)sX)[tid] = v;
    }
    for (int i = tid; i < 4 * HID;    i += THR) sG[i] = g_gate[b * 4 * HID + i];
    for (int i = tid; i < OUTD * HID; i += THR) sC[i] = g_bc[b * OUTD * HID + i];

    // layer-0 weights/scalars for this lane's 4 features
    float4 wd0 = *(const float4*)(Wt0 + 0 * HID + f0);
    float4 wd1 = *(const float4*)(Wt0 + 1 * HID + f0);
    float4 wd2 = *(const float4*)(Wt0 + 2 * HID + f0);
    float4 wd3 = *(const float4*)(Wt0 + 3 * HID + f0);
    float4 bias4 = *(const float4*)(bt0 + f0);
    float4 a4    = *(const float4*)(at + f0);
    float4 wq4   = *(const float4*)(wt + f0);
    __syncthreads();
    float4 g4 = *(const float4*)(sG + f0);

    float* base = sA + (w * 4) * 256;     // this warp's 4 pair rows

    // ---- layer 0 ----
#pragma unroll
    for (int pq = 0; pq < 4; ++pq) {
        float4 x0 = ((float4*)sX)[w * 8 + pq * 2];
        float4 x1 = ((float4*)sX)[w * 8 + pq * 2 + 1];
        float z0[4], z1[4];
        const float* W0 = (const float*)&wd0; const float* W1 = (const float*)&wd1;
        const float* W2 = (const float*)&wd2; const float* W3 = (const float*)&wd3;
        const float* Bv = (const float*)&bias4; const float* Av = (const float*)&a4;
        const float* Qv = (const float*)&wq4;  const float* Gv = (const float*)&g4;
#pragma unroll
        for (int c = 0; c < 4; ++c) {
            z0[c] = fmaf(x0.x, W0[c], fmaf(x0.y, W1[c], fmaf(x0.z, W2[c], fmaf(x0.w, W3[c], Bv[c]))));
            z1[c] = fmaf(x1.x, W0[c], fmaf(x1.y, W1[c], fmaf(x1.z, W2[c], fmaf(x1.w, W3[c], Bv[c]))));
        }
        float r0[4], r1[4];
#pragma unroll
        for (int c = 0; c < 4; ++c) {
            r0[c] = (tanh_ap(z0[c]) + Av[c] * sin_ap(Qv[c] * z0[c])) * Gv[c];
            r1[c] = (tanh_ap(z1[c]) + Av[c] * sin_ap(Qv[c] * z1[c])) * Gv[c];
        }
        float* rp = base + pq * 256 + 2 * f0;
        *(float4*)(rp)     = make_float4(r0[0], r1[0], r0[1], r1[1]);
        *(float4*)(rp + 4) = make_float4(r0[2], r1[2], r0[3], r1[3]);
    }
    __syncwarp();

    // ---- layers 1..3 (rowdy*gate) and final linear (Wtf) ----
    for (int layer = 0; layer < 4; ++layer) {
        const float* Wsrc = (layer < 3) ? (Wt + (size_t)layer * HID * HID) : Wtf;
        const bool fin = (layer == 3);

        __syncthreads();                      // prior sW reads done everywhere
        for (int i = tid; i < (HID * HID) / 4; i += THR)
            ((float4*)sW)[i] = ((const float4*)Wsrc)[i];
        if (!fin) {
            bias4 = *(const float4*)(btv + layer * HID + f0);
            a4    = *(const float4*)(at + (layer + 1) * HID + f0);
            wq4   = *(const float4*)(wt + (layer + 1) * HID + f0);
            g4    = *(const float4*)(sG + (layer + 1) * HID + f0);
        } else {
            bias4 = *(const float4*)(btf + f0);
        }
        __syncthreads();                      // sW ready

        u64 acc[4][4];
#pragma unroll
        for (int pq = 0; pq < 4; ++pq)
#pragma unroll
            for (int c = 0; c < 4; ++c) acc[pq][c] = 0ull;

#pragma unroll 1
        for (int k = 0; k < HID; k += 4) {
            const float* wp = sW + k * HID + f0;
            float4 wr0 = *(const float4*)(wp);
            float4 wr1 = *(const float4*)(wp + HID);
            float4 wr2 = *(const float4*)(wp + 2 * HID);
            float4 wr3 = *(const float4*)(wp + 3 * HID);
            u64 W0x = pk2(wr0.x, wr0.x), W0y = pk2(wr0.y, wr0.y), W0z = pk2(wr0.z, wr0.z), W0w = pk2(wr0.w, wr0.w);
            u64 W1x = pk2(wr1.x, wr1.x), W1y = pk2(wr1.y, wr1.y), W1z = pk2(wr1.z, wr1.z), W1w = pk2(wr1.w, wr1.w);
            u64 W2x = pk2(wr2.x, wr2.x), W2y = pk2(wr2.y, wr2.y), W2z = pk2(wr2.z, wr2.z), W2w = pk2(wr2.w, wr2.w);
            u64 W3x = pk2(wr3.x, wr3.x), W3y = pk2(wr3.y, wr3.y), W3z = pk2(wr3.z, wr3.z), W3w = pk2(wr3.w, wr3.w);
#pragma unroll
            for (int pq = 0; pq < 4; ++pq) {
                const float* rp = base + pq * 256 + 2 * k;
                ulonglong2 aA = *(const ulonglong2*)(rp);       // (k),(k+1)
                ulonglong2 aB = *(const ulonglong2*)(rp + 4);   // (k+2),(k+3)
                fma2(acc[pq][0], aA.x, W0x); fma2(acc[pq][1], aA.x, W0y);
                fma2(acc[pq][2], aA.x, W0z); fma2(acc[pq][3], aA.x, W0w);
                fma2(acc[pq][0], aA.y, W1x); fma2(acc[pq][1], aA.y, W1y);
                fma2(acc[pq][2], aA.y, W1z); fma2(acc[pq][3], aA.y, W1w);
                fma2(acc[pq][0], aB.x, W2x); fma2(acc[pq][1], aB.x, W2y);
                fma2(acc[pq][2], aB.x, W2z); fma2(acc[pq][3], aB.x, W2w);
                fma2(acc[pq][0], aB.y, W3x); fma2(acc[pq][1], aB.y, W3y);
                fma2(acc[pq][2], aB.y, W3z); fma2(acc[pq][3], aB.y, W3w);
            }
        }

        const float* Bv = (const float*)&bias4; const float* Av = (const float*)&a4;
        const float* Qv = (const float*)&wq4;  const float* Gv = (const float*)&g4;
        if (!fin) {
            __syncwarp();                      // warp's reads of its rows done
#pragma unroll
            for (int pq = 0; pq < 4; ++pq) {
                float r0[4], r1[4];
#pragma unroll
                for (int c = 0; c < 4; ++c) {
                    float2 v = up2(acc[pq][c]);
                    float za = v.x + Bv[c], zb = v.y + Bv[c];
                    r0[c] = (tanh_ap(za) + Av[c] * sin_ap(Qv[c] * za)) * Gv[c];
                    r1[c] = (tanh_ap(zb) + Av[c] * sin_ap(Qv[c] * zb)) * Gv[c];
                }
                float* rp = base + pq * 256 + 2 * f0;
                *(float4*)(rp)     = make_float4(r0[0], r1[0], r0[1], r1[1]);
                *(float4*)(rp + 4) = make_float4(r0[2], r1[2], r0[3], r1[3]);
            }
            __syncwarp();
        } else {
            __syncthreads();                   // ALL pair-layout reads done (plain writes overlap)
#pragma unroll
            for (int pq = 0; pq < 4; ++pq) {
                const int p = w * 8 + pq * 2;
#pragma unroll
                for (int c = 0; c < 4; ++c) {
                    float2 v = up2(acc[pq][c]);
                    sA[p * ACTP + f0 + c]       = v.x + Bv[c];
                    sA[(p + 1) * ACTP + f0 + c] = v.y + Bv[c];
                }
            }
        }
    }
    __syncthreads();

    // ---- final contraction: out[p][o] = sum_h trunk[p][h] * bc[o][h] ----
    if (tid < PTS) {
        const int p = tid;
        float o0 = 0.f, o1 = 0.f, o2 = 0.f, o3 = 0.f, o4 = 0.f;
#pragma unroll 4
        for (int h = 0; h < HID; h += 4) {
            float4 a  = *(const float4*)&sA[p * ACTP + h];
            float4 c0 = *(const float4*)&sC[0 * HID + h];
            float4 c1 = *(const float4*)&sC[1 * HID + h];
            float4 c2 = *(const float4*)&sC[2 * HID + h];
            float4 c3 = *(const float4*)&sC[3 * HID + h];
            float4 c4 = *(const float4*)&sC[4 * HID + h];
            o0 += a.x * c0.x + a.y * c0.y + a.z * c0.z + a.w * c0.w;
            o1 += a.x * c1.x + a.y * c1.y + a.z * c1.z + a.w * c1.w;
            o2 += a.x * c2.x + a.y * c2.y + a.z * c2.z + a.w * c2.w;
            o3 += a.x * c3.x + a.y * c3.y + a.z * c3.z + a.w * c3.w;
            o4 += a.x * c4.x + a.y * c4.y + a.z * c4.z + a.w * c4.w;
        }
        const int pglob = p0 + p;
        if (pglob < NPTS) {
            float* dst = out + ((size_t)b * NPTS + pglob) * OUTD;
            dst[0] = o0; dst[1] = o1; dst[2] = o2; dst[3] = o3; dst[4] = o4;
        }
    }
}

// ---------------------------------------------------------------------------
extern "C" void kernel_launch(void* const* d_in, const int* in_sizes, int n_in,
                              void* d_out, int out_size)
{
    const float* coords = (const float*)d_in[0];
    const float* sdf    = (const float*)d_in[1];
    const float* params = (const float*)d_in[2];
    const float* Wb0    = (const float*)d_in[3];
    const float* bb0    = (const float*)d_in[4];
    const float* Wb     = (const float*)d_in[5];
    const float* bbv    = (const float*)d_in[6];
    const float* Wbf    = (const float*)d_in[7];
    const float* bbf    = (const float*)d_in[8];
    const float* ab     = (const float*)d_in[9];
    const float* wb     = (const float*)d_in[10];
    const float* Wt0    = (const float*)d_in[11];
    const float* bt0    = (const float*)d_in[12];
    const float* Wt     = (const float*)d_in[13];
    const float* bt     = (const float*)d_in[14];
    const float* Wtf    = (const float*)d_in[15];
    const float* btf    = (const float*)d_in[16];
    const float* at     = (const float*)d_in[17];
    const float* wt     = (const float*)d_in[18];
    float* out = (float*)d_out;

    const size_t smem_bytes = (size_t)(HID * HID + 16896 + PTS * 4 + 4 * HID + OUTD * HID) * sizeof(float);
    cudaFuncSetAttribute(trunk_kernel, cudaFuncAttributeMaxDynamicSharedMemorySize, (int)smem_bytes);

    branch_kernel<<<BB, 256>>>(params, Wb0, bb0, Wb, bbv, Wbf, bbf, ab, wb);

    dim3 grid(NT, BB);
    trunk_kernel<<<grid, THR, smem_bytes>>>(coords, sdf, Wt0, bt0, Wt, bt,
                                            Wtf, btf, at, wt, out);
}